// round 16
// baseline (speedup 1.0000x reference)
#include <cuda_runtime.h>
#include <math.h>

#define BB   4
#define CC   64
#define NN   4096
#define SCALE 0.125f

typedef unsigned long long u64;

__device__ __forceinline__ u64 pack2(float lo, float hi) {
    u64 r; asm("mov.b64 %0, {%1, %2};" : "=l"(r) : "f"(lo), "f"(hi)); return r;
}
__device__ __forceinline__ void unpack2(u64 v, float &lo, float &hi) {
    asm("mov.b64 {%0, %1}, %2;" : "=f"(lo), "=f"(hi) : "l"(v));
}
__device__ __forceinline__ void fma2(u64 &d, u64 a, u64 b) {
    asm("fma.rn.f32x2 %0, %1, %2, %0;" : "+l"(d) : "l"(a), "l"(b));
}
__device__ __forceinline__ void mul2(u64 &d, u64 a, u64 b) {
    asm("mul.rn.f32x2 %0, %1, %2;" : "=l"(d) : "l"(a), "l"(b));
}

__device__ float g_xp   [BB*CC*NN];
__device__ float g_gap  [BB*CC];
__device__ float g_qT   [BB*CC*NN];
__device__ float g_kT   [BB*CC*NN];
__device__ float g_v    [BB*NN*CC];
__device__ float g_xV   [BB*NN*CC];
__device__ float g_attn1[BB*NN*CC];
__device__ float g_plT  [BB*CC*NN];
__device__ float g_t1   [BB*CC*NN];
__device__ float g_t2   [BB*CC*NN];
__device__ float g_xh   [BB*CC*NN];
__device__ float g_xv2  [BB*CC*NN];
__device__ float g_phT  [BB*CC*NN];
__device__ float g_attn2[BB*NN*CC];
__device__ float g_prom [BB*NN*CC];
__device__ float g_pnorm[BB*CC*NN];
__device__ float g_dsc  [BB*CC*NN];

__device__ __forceinline__ float gelu_f(float x) {
    return 0.5f * x * (1.0f + erff(x * 0.70710678118654752440f));
}

// ---- avgpool 2x2 + per-(b,c) GAP ----
__global__ __launch_bounds__(256) void pool_kernel(const float* __restrict__ X,
                                                   float* __restrict__ xp,
                                                   float* __restrict__ gap)
{
    int bc = blockIdx.x, tid = threadIdx.x;
    const float* p = X + (size_t)bc * (128*128);
    float* o = xp + (size_t)bc * NN;
    float s = 0.f;
    for (int i = tid; i < NN; i += 256) {
        int hp = i >> 6, wp = i & 63;
        const float* q = p + hp*256 + wp*2;
        float v = 0.25f * (q[0] + q[1] + q[128] + q[129]);
        o[i] = v; s += v;
    }
    __shared__ float red[256];
    red[tid] = s; __syncthreads();
    for (int st = 128; st > 0; st >>= 1) {
        if (tid < st) red[tid] += red[tid + st];
        __syncthreads();
    }
    if (tid == 0) gap[bc] = red[0] * (1.0f / 4096.0f);
}

// ---- fused q,k,v (from gap*xp) + x_V (from xp) ----
#define QKVV_SMEM_FLOATS (4096 + 64 + 4*4352)
__global__ __launch_bounds__(256) void qkvv_kernel(
    const float* __restrict__ xp, const float* __restrict__ gap,
    const float* __restrict__ Wq, const float* __restrict__ bq,
    const float* __restrict__ Wk, const float* __restrict__ bk,
    const float* __restrict__ Wv, const float* __restrict__ bv,
    const float* __restrict__ Wo, const float* __restrict__ bo,
    float* __restrict__ qT, float* __restrict__ kT,
    float* __restrict__ v,  float* __restrict__ xV)
{
    extern __shared__ float sm[];
    float* Xs = sm;              // [64 c][64 n]
    float* gs = sm + 4096;
    float* Wt = sm + 4160;       // 4 x [64 c][68 o]

    int b = blockIdx.y, n0 = blockIdx.x << 6, tid = threadIdx.x;
    int ty = tid >> 4, tx = tid & 15;

    const float* Ws[4] = {Wq, Wk, Wv, Wo};
    #pragma unroll
    for (int m = 0; m < 4; m++) {
        const float* W = Ws[m];
        float* wt = Wt + m * 4352;
        for (int idx = tid; idx < 4096; idx += 256) {
            int o = idx >> 6, c = idx & 63;
            wt[c*68 + o] = W[idx];
        }
    }
    if (tid < 64) gs[tid] = gap[b*64 + tid];
    for (int idx = tid; idx < 4096; idx += 256) {
        int c = idx >> 6, nn = idx & 63;
        Xs[idx] = xp[((size_t)(b*64 + c) << 12) + n0 + nn];
    }
    __syncthreads();

    u64 acc2[4][4][2];   // [m][i][jpair]
    #pragma unroll
    for (int m = 0; m < 4; m++)
        #pragma unroll
        for (int i = 0; i < 4; i++) { acc2[m][i][0] = 0ull; acc2[m][i][1] = 0ull; }

    #pragma unroll 4
    for (int c = 0; c < 64; c++) {
        float4 a = *(const float4*)&Xs[(c << 6) + 4*ty];
        float g = gs[c];
        float ar[4] = {a.x, a.y, a.z, a.w};
        u64 ard[4], asd[4];
        #pragma unroll
        for (int i = 0; i < 4; i++) {
            ard[i] = pack2(ar[i], ar[i]);
            float sgl = ar[i] * g;
            asd[i] = pack2(sgl, sgl);
        }
        #pragma unroll
        for (int m = 0; m < 4; m++) {
            ulonglong2 w2 = *(const ulonglong2*)&Wt[m*4352 + c*68 + 4*tx];
            #pragma unroll
            for (int i = 0; i < 4; i++) {
                u64 av = (m < 3) ? asd[i] : ard[i];
                fma2(acc2[m][i][0], av, w2.x);
                fma2(acc2[m][i][1], av, w2.y);
            }
        }
    }

    float acc[4][16];
    #pragma unroll
    for (int m = 0; m < 4; m++)
        #pragma unroll
        for (int i = 0; i < 4; i++) {
            unpack2(acc2[m][i][0], acc[m][i*4+0], acc[m][i*4+1]);
            unpack2(acc2[m][i][1], acc[m][i*4+2], acc[m][i*4+3]);
        }

    #pragma unroll
    for (int i = 0; i < 4; i++) {
        int n = n0 + 4*ty + i;
        #pragma unroll
        for (int j = 0; j < 4; j++) {
            int o = 4*tx + j;
            qT[((size_t)(b*64 + o) << 12) + n] = acc[0][i*4+j] + bq[o];
            kT[((size_t)(b*64 + o) << 12) + n] = acc[1][i*4+j] + bk[o];
        }
        size_t ob = ((size_t)(b*4096 + n)) * 64 + 4*tx;
        float4 rv, rx;
        rv.x = acc[2][i*4+0] + bv[4*tx+0]; rv.y = acc[2][i*4+1] + bv[4*tx+1];
        rv.z = acc[2][i*4+2] + bv[4*tx+2]; rv.w = acc[2][i*4+3] + bv[4*tx+3];
        rx.x = acc[3][i*4+0] + bo[4*tx+0]; rx.y = acc[3][i*4+1] + bo[4*tx+1];
        rx.z = acc[3][i*4+2] + bo[4*tx+2]; rx.w = acc[3][i*4+3] + bo[4*tx+3];
        *(float4*)&v [ob] = rv;
        *(float4*)&xV[ob] = rx;
    }
}

// ---- flash attention: QT,KT [b][c][n]; V,O [b][n][c] ----
#define ATTN_SMEM_FLOATS (8192 + 8192 + 8192 + 128*132)
__global__ __launch_bounds__(256) void attn_kernel(
    const float* __restrict__ QT, const float* __restrict__ KT,
    const float* __restrict__ Vv, float* __restrict__ Oo)
{
    extern __shared__ float sm[];
    float* Qs = sm;               // [64 c][128 q] (pre-scaled)
    float* Ks = Qs + 8192;        // [64 c][128 k]
    float* Vs = Ks + 8192;        // [128 k][64 d]
    float* Ps = Vs + 8192;        // [128 q][132]

    int b = blockIdx.y;
    int q0 = blockIdx.x << 7;
    int tid = threadIdx.x;
    int ty = tid >> 4, tx = tid & 15;

    const float* Qg = QT + (size_t)b * CC * NN;
    const float* Kg = KT + (size_t)b * CC * NN;
    const float* Vg = Vv + (size_t)b * NN * CC;

    for (int idx = tid; idx < 8192; idx += 256) {
        int c = idx >> 7, qq = idx & 127;
        Qs[idx] = Qg[(c << 12) + q0 + qq] * SCALE;
    }

    float m[8], l[8];
    u64 acc2[8][2];
    #pragma unroll
    for (int i = 0; i < 8; i++) {
        m[i] = -1e30f; l[i] = 0.f;
        acc2[i][0] = 0ull; acc2[i][1] = 0ull;
    }

    for (int j0 = 0; j0 < NN; j0 += 128) {
        for (int idx = tid; idx < 8192; idx += 256) {
            int c = idx >> 7, kk = idx & 127;
            Ks[idx] = Kg[(c << 12) + j0 + kk];
        }
        for (int idx = tid; idx < 8192; idx += 256) {
            int kk = idx >> 6, d = idx & 63;
            Vs[idx] = Vg[((size_t)(j0 + kk) << 6) + d];
        }
        __syncthreads();

        // S = Qs^T Ks via packed f32x2 FMA
        u64 s2[8][4];
        #pragma unroll
        for (int i = 0; i < 8; i++)
            #pragma unroll
            for (int jp = 0; jp < 4; jp++) s2[i][jp] = 0ull;

        #pragma unroll 4
        for (int c = 0; c < 64; c++) {
            float4 a0 = *(const float4*)&Qs[(c << 7) + 8*ty];
            float4 a1 = *(const float4*)&Qs[(c << 7) + 8*ty + 4];
            float aa[8] = {a0.x,a0.y,a0.z,a0.w,a1.x,a1.y,a1.z,a1.w};
            u64 ad[8];
            #pragma unroll
            for (int i = 0; i < 8; i++) ad[i] = pack2(aa[i], aa[i]);
            ulonglong2 bb0 = *(const ulonglong2*)&Ks[(c << 7) + 8*tx];
            ulonglong2 bb1 = *(const ulonglong2*)&Ks[(c << 7) + 8*tx + 4];
            u64 b2[4] = {bb0.x, bb0.y, bb1.x, bb1.y};
            #pragma unroll
            for (int i = 0; i < 8; i++)
                #pragma unroll
                for (int jp = 0; jp < 4; jp++)
                    fma2(s2[i][jp], ad[i], b2[jp]);
        }

        // online softmax per row (reduce across tx = low 4 lane bits)
        #pragma unroll
        for (int i = 0; i < 8; i++) {
            float s[8];
            unpack2(s2[i][0], s[0], s[1]);
            unpack2(s2[i][1], s[2], s[3]);
            unpack2(s2[i][2], s[4], s[5]);
            unpack2(s2[i][3], s[6], s[7]);
            float mx = s[0];
            #pragma unroll
            for (int j = 1; j < 8; j++) mx = fmaxf(mx, s[j]);
            mx = fmaxf(mx, __shfl_xor_sync(0xffffffffu, mx, 1));
            mx = fmaxf(mx, __shfl_xor_sync(0xffffffffu, mx, 2));
            mx = fmaxf(mx, __shfl_xor_sync(0xffffffffu, mx, 4));
            mx = fmaxf(mx, __shfl_xor_sync(0xffffffffu, mx, 8));
            float mnew = fmaxf(m[i], mx);
            float corr = __expf(m[i] - mnew);
            m[i] = mnew;
            float rs = 0.f;
            #pragma unroll
            for (int j = 0; j < 8; j++) {
                float p = __expf(s[j] - mnew);
                s[j] = p; rs += p;
            }
            rs += __shfl_xor_sync(0xffffffffu, rs, 1);
            rs += __shfl_xor_sync(0xffffffffu, rs, 2);
            rs += __shfl_xor_sync(0xffffffffu, rs, 4);
            rs += __shfl_xor_sync(0xffffffffu, rs, 8);
            l[i] = l[i]*corr + rs;
            u64 c2 = pack2(corr, corr);
            mul2(acc2[i][0], acc2[i][0], c2);
            mul2(acc2[i][1], acc2[i][1], c2);
            *(float4*)&Ps[(8*ty + i)*132 + 8*tx]     = make_float4(s[0],s[1],s[2],s[3]);
            *(float4*)&Ps[(8*ty + i)*132 + 8*tx + 4] = make_float4(s[4],s[5],s[6],s[7]);
        }
        __syncthreads();

        // O += P V via packed f32x2 FMA (d packed in pairs)
        #pragma unroll 2
        for (int kk = 0; kk < 128; kk++) {
            ulonglong2 vv = *(const ulonglong2*)&Vs[(kk << 6) + 4*tx];
            #pragma unroll
            for (int i = 0; i < 8; i++) {
                float p = Ps[(8*ty + i)*132 + kk];
                u64 p2 = pack2(p, p);
                fma2(acc2[i][0], p2, vv.x);
                fma2(acc2[i][1], p2, vv.y);
            }
        }
        __syncthreads();
    }

    #pragma unroll
    for (int i = 0; i < 8; i++) {
        float inv = 1.0f / l[i];
        float a0, a1, a2, a3;
        unpack2(acc2[i][0], a0, a1);
        unpack2(acc2[i][1], a2, a3);
        float4 r;
        r.x = a0*inv; r.y = a1*inv; r.z = a2*inv; r.w = a3*inv;
        *(float4*)&Oo[((size_t)(b*NN + q0 + 8*ty + i) << 6) + 4*tx] = r;
    }
}

// ---- linear: y = X @ W^T + b (+res); X [b][n][c] ----
__global__ __launch_bounds__(256) void lin_kernel(
    const float* __restrict__ X, const float* __restrict__ W,
    const float* __restrict__ bias, const float* __restrict__ res,
    float* __restrict__ out, int transpose_out)
{
    __shared__ float Xs[64*68];   // [c][nn]
    __shared__ float Wt[64*68];   // [c][o]
    int b = blockIdx.y, n0 = blockIdx.x << 6, tid = threadIdx.x;
    int ty = tid >> 4, tx = tid & 15;

    for (int idx = tid; idx < 4096; idx += 256) {
        int nn = idx >> 6, c = idx & 63;
        Xs[c*68 + nn] = X[((size_t)(b*4096 + n0 + nn)) * 64 + c];
        Wt[c*68 + nn] = W[idx];   // idx = o*64+c with o==nn
    }
    __syncthreads();

    u64 acc2[4][2];
    #pragma unroll
    for (int i = 0; i < 4; i++) { acc2[i][0] = 0ull; acc2[i][1] = 0ull; }
    #pragma unroll 8
    for (int c = 0; c < 64; c++) {
        float4 a = *(const float4*)&Xs[c*68 + 4*ty];
        ulonglong2 w2 = *(const ulonglong2*)&Wt[c*68 + 4*tx];
        float af[4] = {a.x,a.y,a.z,a.w};
        #pragma unroll
        for (int i = 0; i < 4; i++) {
            u64 ad = pack2(af[i], af[i]);
            fma2(acc2[i][0], ad, w2.x);
            fma2(acc2[i][1], ad, w2.y);
        }
    }
    float acc[16];
    #pragma unroll
    for (int i = 0; i < 4; i++) {
        unpack2(acc2[i][0], acc[i*4+0], acc[i*4+1]);
        unpack2(acc2[i][1], acc[i*4+2], acc[i*4+3]);
    }

    if (transpose_out) {
        #pragma unroll
        for (int i = 0; i < 4; i++)
            #pragma unroll
            for (int j = 0; j < 4; j++) {
                int o = 4*tx + j;
                out[((size_t)(b*64 + o) << 12) + n0 + 4*ty + i] = acc[i*4+j] + bias[o];
            }
    } else {
        #pragma unroll
        for (int i = 0; i < 4; i++) {
            size_t ob = ((size_t)(b*4096 + n0 + 4*ty + i)) * 64 + 4*tx;
            float4 r;
            r.x = acc[i*4+0] + bias[4*tx+0];
            r.y = acc[i*4+1] + bias[4*tx+1];
            r.z = acc[i*4+2] + bias[4*tx+2];
            r.w = acc[i*4+3] + bias[4*tx+3];
            if (res) { r.x += res[ob]; r.y += res[ob+1]; r.z += res[ob+2]; r.w += res[ob+3]; }
            *(float4*)&out[ob] = r;
        }
    }
}

// ---- 1x1 conv: out[b][o][n] = W[o][c] X[b][c][n] + b (+res); optional gelu on input sum ----
__global__ __launch_bounds__(256) void pw_kernel(
    const float* __restrict__ X1, const float* __restrict__ X2,
    const float* __restrict__ W, const float* __restrict__ bias,
    const float* __restrict__ res, float* __restrict__ out, int gelu_in)
{
    __shared__ float Xs[4096];    // [c][nn]
    __shared__ float Wt[64*68];   // [ci][o]
    int b = blockIdx.y, n0 = blockIdx.x << 6, tid = threadIdx.x;
    int ty = tid >> 4, tx = tid & 15;

    for (int idx = tid; idx < 4096; idx += 256) {
        int c = idx >> 6, nn = idx & 63;
        size_t g = ((size_t)(b*64 + c) << 12) + n0 + nn;
        float v = X1[g];
        if (X2) v += X2[g];
        if (gelu_in) v = gelu_f(v);
        Xs[idx] = v;
        Wt[nn*68 + c] = W[idx];   // idx = o*64+ci with o==c, ci==nn
    }
    __syncthreads();

    u64 acc2[4][2];
    #pragma unroll
    for (int i = 0; i < 4; i++) { acc2[i][0] = 0ull; acc2[i][1] = 0ull; }
    #pragma unroll 8
    for (int c = 0; c < 64; c++) {
        float4 w = *(const float4*)&Wt[c*68 + 4*ty];
        ulonglong2 x2 = *(const ulonglong2*)&Xs[(c << 6) + 4*tx];
        float wf[4] = {w.x,w.y,w.z,w.w};
        #pragma unroll
        for (int i = 0; i < 4; i++) {
            u64 wd = pack2(wf[i], wf[i]);
            fma2(acc2[i][0], wd, x2.x);
            fma2(acc2[i][1], wd, x2.y);
        }
    }
    float acc[16];
    #pragma unroll
    for (int i = 0; i < 4; i++) {
        unpack2(acc2[i][0], acc[i*4+0], acc[i*4+1]);
        unpack2(acc2[i][1], acc[i*4+2], acc[i*4+3]);
    }

    #pragma unroll
    for (int i = 0; i < 4; i++) {
        int o = 4*ty + i;
        float bo_ = bias[o];
        size_t ob = ((size_t)(b*64 + o) << 12) + n0 + 4*tx;
        float4 r;
        r.x = acc[i*4+0] + bo_; r.y = acc[i*4+1] + bo_;
        r.z = acc[i*4+2] + bo_; r.w = acc[i*4+3] + bo_;
        if (res) { r.x += res[ob]; r.y += res[ob+1]; r.z += res[ob+2]; r.w += res[ob+3]; }
        *(float4*)&out[ob] = r;
    }
}

// ---- depthwise convs (64x64 planes, layout [b][c][h][w]) ----
__global__ __launch_bounds__(256) void dw5v_kernel(const float* __restrict__ X,
    const float* __restrict__ w, const float* __restrict__ bias, float* __restrict__ out)
{
    int idx = blockIdx.x*256 + threadIdx.x;
    int wc = idx & 63, h = (idx >> 6) & 63, c = (idx >> 12) & 63;
    const float* p = X + (idx & ~4095);
    float s = bias[c];
    #pragma unroll
    for (int t = 0; t < 5; t++) {
        int hh = h - 2 + t;
        if (hh >= 0 && hh < 64) s += w[c*5 + t] * p[(hh << 6) + wc];
    }
    out[idx] = s;
}

__global__ __launch_bounds__(256) void dw5h_kernel(const float* __restrict__ X,
    const float* __restrict__ w, const float* __restrict__ bias, float* __restrict__ out)
{
    int idx = blockIdx.x*256 + threadIdx.x;
    int wc = idx & 63, h = (idx >> 6) & 63, c = (idx >> 12) & 63;
    const float* p = X + (idx & ~4095);
    float s = bias[c];
    #pragma unroll
    for (int t = 0; t < 5; t++) {
        int ww = wc - 2 + t;
        if (ww >= 0 && ww < 64) s += w[c*5 + t] * p[(h << 6) + ww];
    }
    out[idx] = s;
}

__global__ __launch_bounds__(256) void dw33_kernel(const float* __restrict__ X,
    const float* __restrict__ w, const float* __restrict__ bias, float* __restrict__ out)
{
    int idx = blockIdx.x*256 + threadIdx.x;
    int wc = idx & 63, h = (idx >> 6) & 63, c = (idx >> 12) & 63;
    const float* p = X + (idx & ~4095);
    float s = bias[c];
    #pragma unroll
    for (int ky = 0; ky < 3; ky++) {
        int hh = h - 1 + ky;
        if (hh < 0 || hh >= 64) continue;
        #pragma unroll
        for (int kx = 0; kx < 3; kx++) {
            int ww = wc - 1 + kx;
            if (ww >= 0 && ww < 64) s += w[c*9 + ky*3 + kx] * p[(hh << 6) + ww];
        }
    }
    out[idx] = s;
}

// ---- LayerNorm over C; in [b][n][c], out [b][c][n] ----
__global__ __launch_bounds__(256) void ln_kernel(const float* __restrict__ X,
    const float* __restrict__ gam, const float* __restrict__ bet, float* __restrict__ out)
{
    __shared__ float Ts[64*66];
    int b = blockIdx.y, n0 = blockIdx.x << 6, tid = threadIdx.x;
    for (int idx = tid; idx < 4096; idx += 256) {
        int nn = idx >> 6, c = idx & 63;
        Ts[nn*66 + c] = X[((size_t)(b*4096 + n0 + nn)) * 64 + c];
    }
    __syncthreads();
    int row = tid >> 2, q = tid & 3;
    float s = 0.f, s2 = 0.f;
    #pragma unroll
    for (int k = 0; k < 16; k++) {
        float v = Ts[row*66 + q*16 + k];
        s += v; s2 += v*v;
    }
    s  += __shfl_xor_sync(0xffffffffu, s, 1);
    s  += __shfl_xor_sync(0xffffffffu, s, 2);
    s2 += __shfl_xor_sync(0xffffffffu, s2, 1);
    s2 += __shfl_xor_sync(0xffffffffu, s2, 2);
    float mu  = s * (1.0f/64.0f);
    float var = fmaxf(s2 * (1.0f/64.0f) - mu*mu, 0.f);
    float inv = rsqrtf(var + 1e-5f);
    #pragma unroll
    for (int k = 0; k < 16; k++) {
        int o = row*66 + q*16 + k;
        Ts[o] = (Ts[o] - mu) * inv;
    }
    __syncthreads();
    for (int idx = tid; idx < 4096; idx += 256) {
        int c = idx >> 6, nn = idx & 63;
        out[((size_t)(b*64 + c) << 12) + n0 + nn] = Ts[nn*66 + c] * gam[c] + bet[c];
    }
}

// ---- bilinear upsample x2, align_corners=True ----
__global__ __launch_bounds__(256) void up_kernel(const float* __restrict__ X,
                                                 float* __restrict__ out)
{
    int idx = blockIdx.x*256 + threadIdx.x;
    int wo = idx & 127, ho = (idx >> 7) & 127;
    int plane = idx >> 14;
    const float st = 63.0f / 127.0f;
    float fy = ho * st, fx = wo * st;
    int y0 = (int)fy, x0 = (int)fx;
    float wy = fy - y0, wx = fx - x0;
    int y1 = min(y0 + 1, 63), x1 = min(x0 + 1, 63);
    const float* p = X + (size_t)plane * 4096;
    float a = p[(y0 << 6) + x0], bv = p[(y1 << 6) + x0];
    float c = p[(y0 << 6) + x1], d = p[(y1 << 6) + x1];
    out[idx] = (a*(1.f - wy) + bv*wy)*(1.f - wx) + (c*(1.f - wy) + d*wy)*wx;
}

extern "C" void kernel_launch(void* const* d_in, const int* in_sizes, int n_in,
                              void* d_out, int out_size)
{
    const float* x       = (const float*)d_in[0];
    const float* Wq      = (const float*)d_in[1];
    const float* bq      = (const float*)d_in[2];
    const float* Wk      = (const float*)d_in[3];
    const float* bk      = (const float*)d_in[4];
    const float* Wv      = (const float*)d_in[5];
    const float* bv_     = (const float*)d_in[6];
    const float* Wl      = (const float*)d_in[7];
    const float* bl      = (const float*)d_in[8];
    const float* Wo      = (const float*)d_in[9];
    const float* bo      = (const float*)d_in[10];
    const float* Wp      = (const float*)d_in[11];
    const float* bp      = (const float*)d_in[12];
    const float* sch_dw  = (const float*)d_in[13];
    const float* sch_dwb = (const float*)d_in[14];
    const float* sch_pw  = (const float*)d_in[15];
    const float* sch_pwb = (const float*)d_in[16];
    const float* scv_dw  = (const float*)d_in[17];
    const float* scv_dwb = (const float*)d_in[18];
    const float* scv_pw  = (const float*)d_in[19];
    const float* scv_pwb = (const float*)d_in[20];
    const float* convh_w = (const float*)d_in[21];
    const float* convh_b = (const float*)d_in[22];
    const float* dsc_dw  = (const float*)d_in[23];
    const float* dsc_dwb = (const float*)d_in[24];
    const float* dsc_pw  = (const float*)d_in[25];
    const float* dsc_pwb = (const float*)d_in[26];
    const float* ln_g    = (const float*)d_in[27];
    const float* ln_b    = (const float*)d_in[28];
    float* out = (float*)d_out;

    float *xp, *gap, *qT, *kT, *v, *xV, *attn1, *plT, *t1, *t2, *xh, *xv2,
          *phT, *attn2, *prom, *pnorm, *dsc;
    cudaGetSymbolAddress((void**)&xp,    g_xp);
    cudaGetSymbolAddress((void**)&gap,   g_gap);
    cudaGetSymbolAddress((void**)&qT,    g_qT);
    cudaGetSymbolAddress((void**)&kT,    g_kT);
    cudaGetSymbolAddress((void**)&v,     g_v);
    cudaGetSymbolAddress((void**)&xV,    g_xV);
    cudaGetSymbolAddress((void**)&attn1, g_attn1);
    cudaGetSymbolAddress((void**)&plT,   g_plT);
    cudaGetSymbolAddress((void**)&t1,    g_t1);
    cudaGetSymbolAddress((void**)&t2,    g_t2);
    cudaGetSymbolAddress((void**)&xh,    g_xh);
    cudaGetSymbolAddress((void**)&xv2,   g_xv2);
    cudaGetSymbolAddress((void**)&phT,   g_phT);
    cudaGetSymbolAddress((void**)&attn2, g_attn2);
    cudaGetSymbolAddress((void**)&prom,  g_prom);
    cudaGetSymbolAddress((void**)&pnorm, g_pnorm);
    cudaGetSymbolAddress((void**)&dsc,   g_dsc);

    const int QKVV_SMEM = QKVV_SMEM_FLOATS * 4;
    const int ATTN_SMEM = ATTN_SMEM_FLOATS * 4;
    static int attr_done = 0;
    if (!attr_done) {
        cudaFuncSetAttribute(qkvv_kernel, cudaFuncAttributeMaxDynamicSharedMemorySize, QKVV_SMEM);
        cudaFuncSetAttribute(attn_kernel, cudaFuncAttributeMaxDynamicSharedMemorySize, ATTN_SMEM);
        attr_done = 1;
    }

    pool_kernel<<<BB*CC, 256>>>(x, xp, gap);
    qkvv_kernel<<<dim3(64, BB), 256, QKVV_SMEM>>>(xp, gap, Wq, bq, Wk, bk, Wv, bv_, Wo, bo,
                                                  qT, kT, v, xV);
    attn_kernel<<<dim3(32, BB), 256, ATTN_SMEM>>>(qT, kT, v, attn1);
    lin_kernel<<<dim3(64, BB), 256>>>(attn1, Wl, bl, nullptr, plT, 1);
    dw5v_kernel<<<BB*CC*NN/256, 256>>>(xp, sch_dw, sch_dwb, t1);
    pw_kernel<<<dim3(64, BB), 256>>>(t1, nullptr, sch_pw, sch_pwb, nullptr, xh, 1);
    dw5h_kernel<<<BB*CC*NN/256, 256>>>(xp, scv_dw, scv_dwb, t2);
    pw_kernel<<<dim3(64, BB), 256>>>(t2, nullptr, scv_pw, scv_pwb, nullptr, xv2, 1);
    pw_kernel<<<dim3(64, BB), 256>>>(xh, xv2, convh_w, convh_b, nullptr, phT, 0);
    attn_kernel<<<dim3(32, BB), 256, ATTN_SMEM>>>(phT, plT, xV, attn2);
    lin_kernel<<<dim3(64, BB), 256>>>(attn2, Wp, bp, xV, prom, 0);
    ln_kernel<<<dim3(64, BB), 256>>>(prom, ln_g, ln_b, pnorm);
    dw33_kernel<<<BB*CC*NN/256, 256>>>(pnorm, dsc_dw, dsc_dwb, t1);
    pw_kernel<<<dim3(64, BB), 256>>>(t1, nullptr, dsc_pw, dsc_pwb, pnorm, dsc, 1);
    up_kernel<<<BB*CC*128*128/256, 256>>>(dsc, out);
}

// round 17
// speedup vs baseline: 2.4845x; 2.4845x over previous
#include <cuda_runtime.h>
#include <math.h>

#define BB   4
#define CC   64
#define NN   4096
#define SCALE 0.125f

typedef unsigned long long u64;
typedef unsigned int u32;

__device__ __forceinline__ u64 pack2(float lo, float hi) {
    u64 r; asm("mov.b64 %0, {%1, %2};" : "=l"(r) : "f"(lo), "f"(hi)); return r;
}
__device__ __forceinline__ void unpack2(u64 v, float &lo, float &hi) {
    asm("mov.b64 {%0, %1}, %2;" : "=f"(lo), "=f"(hi) : "l"(v));
}
__device__ __forceinline__ void fma2(u64 &d, u64 a, u64 b) {
    asm("fma.rn.f32x2 %0, %1, %2, %0;" : "+l"(d) : "l"(a), "l"(b));
}
__device__ __forceinline__ u32 tf32_rna(float f) {
    u32 u; asm("cvt.rna.tf32.f32 %0, %1;" : "=r"(u) : "f"(f)); return u;
}
__device__ __forceinline__ void mma_tf32(float* d, const u32* a, u32 b0, u32 b1) {
    asm("mma.sync.aligned.m16n8k8.row.col.f32.tf32.tf32.f32 "
        "{%0,%1,%2,%3}, {%4,%5,%6,%7}, {%8,%9}, {%0,%1,%2,%3};"
        : "+f"(d[0]), "+f"(d[1]), "+f"(d[2]), "+f"(d[3])
        : "r"(a[0]), "r"(a[1]), "r"(a[2]), "r"(a[3]), "r"(b0), "r"(b1));
}

__device__ float g_xp   [BB*CC*NN];
__device__ float g_gap  [BB*CC];
__device__ float g_qT   [BB*CC*NN];
__device__ float g_kT   [BB*CC*NN];
__device__ float g_v    [BB*NN*CC];
__device__ float g_xV   [BB*NN*CC];
__device__ float g_attn1[BB*NN*CC];
__device__ float g_plT  [BB*CC*NN];
__device__ float g_t1   [BB*CC*NN];
__device__ float g_t2   [BB*CC*NN];
__device__ float g_xh   [BB*CC*NN];
__device__ float g_xv2  [BB*CC*NN];
__device__ float g_phT  [BB*CC*NN];
__device__ float g_attn2[BB*NN*CC];
__device__ float g_prom [BB*NN*CC];
__device__ float g_pnorm[BB*CC*NN];
__device__ float g_dsc  [BB*CC*NN];

__device__ __forceinline__ float gelu_f(float x) {
    return 0.5f * x * (1.0f + erff(x * 0.70710678118654752440f));
}

// ---- avgpool 2x2 + per-(b,c) GAP ----
__global__ __launch_bounds__(256) void pool_kernel(const float* __restrict__ X,
                                                   float* __restrict__ xp,
                                                   float* __restrict__ gap)
{
    int bc = blockIdx.x, tid = threadIdx.x;
    const float* p = X + (size_t)bc * (128*128);
    float* o = xp + (size_t)bc * NN;
    float s = 0.f;
    for (int i = tid; i < NN; i += 256) {
        int hp = i >> 6, wp = i & 63;
        const float* q = p + hp*256 + wp*2;
        float v = 0.25f * (q[0] + q[1] + q[128] + q[129]);
        o[i] = v; s += v;
    }
    __shared__ float red[256];
    red[tid] = s; __syncthreads();
    for (int st = 128; st > 0; st >>= 1) {
        if (tid < st) red[tid] += red[tid + st];
        __syncthreads();
    }
    if (tid == 0) gap[bc] = red[0] * (1.0f / 4096.0f);
}

// ---- fused q,k,v (from gap*xp) + x_V (from xp) ----
#define QKVV_SMEM_FLOATS (4096 + 64 + 4*4352)
__global__ __launch_bounds__(256) void qkvv_kernel(
    const float* __restrict__ xp, const float* __restrict__ gap,
    const float* __restrict__ Wq, const float* __restrict__ bq,
    const float* __restrict__ Wk, const float* __restrict__ bk,
    const float* __restrict__ Wv, const float* __restrict__ bv,
    const float* __restrict__ Wo, const float* __restrict__ bo,
    float* __restrict__ qT, float* __restrict__ kT,
    float* __restrict__ v,  float* __restrict__ xV)
{
    extern __shared__ float sm[];
    float* Xs = sm;              // [64 c][64 n]
    float* gs = sm + 4096;
    float* Wt = sm + 4160;       // 4 x [64 c][68 o]

    int b = blockIdx.y, n0 = blockIdx.x << 6, tid = threadIdx.x;
    int ty = tid >> 4, tx = tid & 15;

    const float* Ws[4] = {Wq, Wk, Wv, Wo};
    #pragma unroll
    for (int m = 0; m < 4; m++) {
        const float* W = Ws[m];
        float* wt = Wt + m * 4352;
        for (int idx = tid; idx < 4096; idx += 256) {
            int o = idx >> 6, c = idx & 63;
            wt[c*68 + o] = W[idx];
        }
    }
    if (tid < 64) gs[tid] = gap[b*64 + tid];
    for (int idx = tid; idx < 4096; idx += 256) {
        int c = idx >> 6, nn = idx & 63;
        Xs[idx] = xp[((size_t)(b*64 + c) << 12) + n0 + nn];
    }
    __syncthreads();

    u64 acc2[4][4][2];
    #pragma unroll
    for (int m = 0; m < 4; m++)
        #pragma unroll
        for (int i = 0; i < 4; i++) { acc2[m][i][0] = 0ull; acc2[m][i][1] = 0ull; }

    #pragma unroll 4
    for (int c = 0; c < 64; c++) {
        float4 a = *(const float4*)&Xs[(c << 6) + 4*ty];
        float g = gs[c];
        float ar[4] = {a.x, a.y, a.z, a.w};
        u64 ard[4], asd[4];
        #pragma unroll
        for (int i = 0; i < 4; i++) {
            ard[i] = pack2(ar[i], ar[i]);
            float sgl = ar[i] * g;
            asd[i] = pack2(sgl, sgl);
        }
        #pragma unroll
        for (int m = 0; m < 4; m++) {
            ulonglong2 w2 = *(const ulonglong2*)&Wt[m*4352 + c*68 + 4*tx];
            #pragma unroll
            for (int i = 0; i < 4; i++) {
                u64 av = (m < 3) ? asd[i] : ard[i];
                fma2(acc2[m][i][0], av, w2.x);
                fma2(acc2[m][i][1], av, w2.y);
            }
        }
    }

    float acc[4][16];
    #pragma unroll
    for (int m = 0; m < 4; m++)
        #pragma unroll
        for (int i = 0; i < 4; i++) {
            unpack2(acc2[m][i][0], acc[m][i*4+0], acc[m][i*4+1]);
            unpack2(acc2[m][i][1], acc[m][i*4+2], acc[m][i*4+3]);
        }

    #pragma unroll
    for (int i = 0; i < 4; i++) {
        int n = n0 + 4*ty + i;
        #pragma unroll
        for (int j = 0; j < 4; j++) {
            int o = 4*tx + j;
            qT[((size_t)(b*64 + o) << 12) + n] = acc[0][i*4+j] + bq[o];
            kT[((size_t)(b*64 + o) << 12) + n] = acc[1][i*4+j] + bk[o];
        }
        size_t ob = ((size_t)(b*4096 + n)) * 64 + 4*tx;
        float4 rv, rx;
        rv.x = acc[2][i*4+0] + bv[4*tx+0]; rv.y = acc[2][i*4+1] + bv[4*tx+1];
        rv.z = acc[2][i*4+2] + bv[4*tx+2]; rv.w = acc[2][i*4+3] + bv[4*tx+3];
        rx.x = acc[3][i*4+0] + bo[4*tx+0]; rx.y = acc[3][i*4+1] + bo[4*tx+1];
        rx.z = acc[3][i*4+2] + bo[4*tx+2]; rx.w = acc[3][i*4+3] + bo[4*tx+3];
        *(float4*)&v [ob] = rv;
        *(float4*)&xV[ob] = rx;
    }
}

// ---- tensor-core flash attention (tf32 mma.sync) ----
// QT,KT: [b][c][n]; V,O: [b][n][c]
#define KS_STRIDE 72
#define PS_STRIDE 76
#define ATTN_TC_SMEM ((64*KS_STRIDE + 64*KS_STRIDE + 128*PS_STRIDE) * 4)
__global__ __launch_bounds__(256) void attn_tc_kernel(
    const float* __restrict__ QT, const float* __restrict__ KT,
    const float* __restrict__ Vv, float* __restrict__ Oo)
{
    extern __shared__ float sm[];
    float* Ks = sm;                          // [64 c][72]
    float* Vs = sm + 64*KS_STRIDE;           // [64 k][72]
    float* Ps = sm + 2*64*KS_STRIDE;         // [128 q][76]

    int b = blockIdx.y, q0 = blockIdx.x << 7;
    int tid = threadIdx.x, w = tid >> 5, lane = tid & 31;
    int gid = lane >> 2, qc = lane & 3;      // groupID / quad-col

    const float* Qg = QT + (size_t)b * CC * NN;
    const float* Kg = KT + (size_t)b * CC * NN;
    const float* Vg = Vv + (size_t)b * NN * CC;

    // Q A-fragments for all 8 k-steps (tf32, pre-scaled), loaded once
    u32 qa[8][4];
    int qrow = q0 + w*16 + gid;
    #pragma unroll
    for (int ks = 0; ks < 8; ks++) {
        int c = ks*8 + qc;
        qa[ks][0] = tf32_rna(Qg[c*4096 + qrow]       * SCALE);
        qa[ks][1] = tf32_rna(Qg[c*4096 + qrow + 8]   * SCALE);
        qa[ks][2] = tf32_rna(Qg[(c+4)*4096 + qrow]   * SCALE);
        qa[ks][3] = tf32_rna(Qg[(c+4)*4096 + qrow+8] * SCALE);
    }

    float o[8][4];
    #pragma unroll
    for (int nt = 0; nt < 8; nt++) { o[nt][0]=0.f; o[nt][1]=0.f; o[nt][2]=0.f; o[nt][3]=0.f; }
    float m0 = -1e30f, m1 = -1e30f, l0 = 0.f, l1 = 0.f;

    for (int j0 = 0; j0 < NN; j0 += 64) {
        __syncthreads();
        // stage K tile [64 c][64 keys] and V tile [64 k][64 d], tf32-rounded
        #pragma unroll
        for (int it = 0; it < 4; it++) {
            int idx = tid + it*256;              // 0..1023
            int r  = idx >> 4;
            int cc4 = (idx & 15) << 2;
            float4 tk = *(const float4*)&Kg[r*4096 + j0 + cc4];
            float* dk = &Ks[r*KS_STRIDE + cc4];
            dk[0] = __uint_as_float(tf32_rna(tk.x));
            dk[1] = __uint_as_float(tf32_rna(tk.y));
            dk[2] = __uint_as_float(tf32_rna(tk.z));
            dk[3] = __uint_as_float(tf32_rna(tk.w));
            float4 tv = *(const float4*)&Vg[((size_t)(j0 + r)) * 64 + cc4];
            float* dv = &Vs[r*KS_STRIDE + cc4];
            dv[0] = __uint_as_float(tf32_rna(tv.x));
            dv[1] = __uint_as_float(tf32_rna(tv.y));
            dv[2] = __uint_as_float(tf32_rna(tv.z));
            dv[3] = __uint_as_float(tf32_rna(tv.w));
        }
        __syncthreads();

        // S = Q K^T  (8 n-tiles of 8 keys; ks outer keeps accumulators independent inner)
        float sacc[8][4];
        #pragma unroll
        for (int nt = 0; nt < 8; nt++) { sacc[nt][0]=0.f; sacc[nt][1]=0.f; sacc[nt][2]=0.f; sacc[nt][3]=0.f; }
        #pragma unroll
        for (int ks = 0; ks < 8; ks++) {
            const float* kr0 = &Ks[(ks*8 + qc)*KS_STRIDE + gid];
            const float* kr1 = &Ks[(ks*8 + qc + 4)*KS_STRIDE + gid];
            #pragma unroll
            for (int nt = 0; nt < 8; nt++) {
                u32 b0 = __float_as_uint(kr0[nt*8]);
                u32 b1 = __float_as_uint(kr1[nt*8]);
                mma_tf32(sacc[nt], qa[ks], b0, b1);
            }
        }

        // online softmax (rows r0 = gid and gid+8 of this warp's 16-query stripe)
        float mx0 = -1e30f, mx1 = -1e30f;
        #pragma unroll
        for (int nt = 0; nt < 8; nt++) {
            mx0 = fmaxf(mx0, fmaxf(sacc[nt][0], sacc[nt][1]));
            mx1 = fmaxf(mx1, fmaxf(sacc[nt][2], sacc[nt][3]));
        }
        mx0 = fmaxf(mx0, __shfl_xor_sync(0xffffffffu, mx0, 1));
        mx0 = fmaxf(mx0, __shfl_xor_sync(0xffffffffu, mx0, 2));
        mx1 = fmaxf(mx1, __shfl_xor_sync(0xffffffffu, mx1, 1));
        mx1 = fmaxf(mx1, __shfl_xor_sync(0xffffffffu, mx1, 2));
        float mn0 = fmaxf(m0, mx0), mn1 = fmaxf(m1, mx1);
        float corr0 = __expf(m0 - mn0), corr1 = __expf(m1 - mn1);
        m0 = mn0; m1 = mn1;
        float rs0 = 0.f, rs1 = 0.f;
        float* prow0 = &Ps[(w*16 + gid)*PS_STRIDE + 2*qc];
        float* prow1 = prow0 + 8*PS_STRIDE;
        #pragma unroll
        for (int nt = 0; nt < 8; nt++) {
            float p0 = __expf(sacc[nt][0] - m0), p1 = __expf(sacc[nt][1] - m0);
            float p2 = __expf(sacc[nt][2] - m1), p3 = __expf(sacc[nt][3] - m1);
            rs0 += p0 + p1; rs1 += p2 + p3;
            float2 w0, w1;
            w0.x = __uint_as_float(tf32_rna(p0)); w0.y = __uint_as_float(tf32_rna(p1));
            w1.x = __uint_as_float(tf32_rna(p2)); w1.y = __uint_as_float(tf32_rna(p3));
            *(float2*)&prow0[nt*8] = w0;
            *(float2*)&prow1[nt*8] = w1;
        }
        rs0 += __shfl_xor_sync(0xffffffffu, rs0, 1);
        rs0 += __shfl_xor_sync(0xffffffffu, rs0, 2);
        rs1 += __shfl_xor_sync(0xffffffffu, rs1, 1);
        rs1 += __shfl_xor_sync(0xffffffffu, rs1, 2);
        l0 = l0*corr0 + rs0; l1 = l1*corr1 + rs1;
        #pragma unroll
        for (int nt = 0; nt < 8; nt++) {
            o[nt][0] *= corr0; o[nt][1] *= corr0;
            o[nt][2] *= corr1; o[nt][3] *= corr1;
        }
        __syncwarp();   // Ps is per-warp private rows; only warp-visibility needed

        // O += P V
        #pragma unroll
        for (int ks = 0; ks < 8; ks++) {
            u32 a[4];
            int pr = (w*16 + gid)*PS_STRIDE + ks*8;
            a[0] = __float_as_uint(Ps[pr + qc]);
            a[1] = __float_as_uint(Ps[pr + 8*PS_STRIDE + qc]);
            a[2] = __float_as_uint(Ps[pr + qc + 4]);
            a[3] = __float_as_uint(Ps[pr + 8*PS_STRIDE + qc + 4]);
            const float* vr0 = &Vs[(ks*8 + qc)*KS_STRIDE + gid];
            const float* vr1 = &Vs[(ks*8 + qc + 4)*KS_STRIDE + gid];
            #pragma unroll
            for (int nt = 0; nt < 8; nt++) {
                u32 b0 = __float_as_uint(vr0[nt*8]);
                u32 b1 = __float_as_uint(vr1[nt*8]);
                mma_tf32(o[nt], a, b0, b1);
            }
        }
    }

    float inv0 = 1.0f / l0, inv1 = 1.0f / l1;
    int row0 = q0 + w*16 + gid;
    #pragma unroll
    for (int nt = 0; nt < 8; nt++) {
        int d = nt*8 + 2*qc;
        float2 r0v, r1v;
        r0v.x = o[nt][0]*inv0; r0v.y = o[nt][1]*inv0;
        r1v.x = o[nt][2]*inv1; r1v.y = o[nt][3]*inv1;
        *(float2*)&Oo[((size_t)(b*NN + row0))     * 64 + d] = r0v;
        *(float2*)&Oo[((size_t)(b*NN + row0 + 8)) * 64 + d] = r1v;
    }
}

// ---- linear: y = X @ W^T + b (+res); X [b][n][c] ----
__global__ __launch_bounds__(256) void lin_kernel(
    const float* __restrict__ X, const float* __restrict__ W,
    const float* __restrict__ bias, const float* __restrict__ res,
    float* __restrict__ out, int transpose_out)
{
    __shared__ float Xs[64*68];
    __shared__ float Wt[64*68];
    int b = blockIdx.y, n0 = blockIdx.x << 6, tid = threadIdx.x;
    int ty = tid >> 4, tx = tid & 15;

    for (int idx = tid; idx < 4096; idx += 256) {
        int nn = idx >> 6, c = idx & 63;
        Xs[c*68 + nn] = X[((size_t)(b*4096 + n0 + nn)) * 64 + c];
        Wt[c*68 + nn] = W[idx];
    }
    __syncthreads();

    u64 acc2[4][2];
    #pragma unroll
    for (int i = 0; i < 4; i++) { acc2[i][0] = 0ull; acc2[i][1] = 0ull; }
    #pragma unroll 8
    for (int c = 0; c < 64; c++) {
        float4 a = *(const float4*)&Xs[c*68 + 4*ty];
        ulonglong2 w2 = *(const ulonglong2*)&Wt[c*68 + 4*tx];
        float af[4] = {a.x,a.y,a.z,a.w};
        #pragma unroll
        for (int i = 0; i < 4; i++) {
            u64 ad = pack2(af[i], af[i]);
            fma2(acc2[i][0], ad, w2.x);
            fma2(acc2[i][1], ad, w2.y);
        }
    }
    float acc[16];
    #pragma unroll
    for (int i = 0; i < 4; i++) {
        unpack2(acc2[i][0], acc[i*4+0], acc[i*4+1]);
        unpack2(acc2[i][1], acc[i*4+2], acc[i*4+3]);
    }

    if (transpose_out) {
        #pragma unroll
        for (int i = 0; i < 4; i++)
            #pragma unroll
            for (int j = 0; j < 4; j++) {
                int o = 4*tx + j;
                out[((size_t)(b*64 + o) << 12) + n0 + 4*ty + i] = acc[i*4+j] + bias[o];
            }
    } else {
        #pragma unroll
        for (int i = 0; i < 4; i++) {
            size_t ob = ((size_t)(b*4096 + n0 + 4*ty + i)) * 64 + 4*tx;
            float4 r;
            r.x = acc[i*4+0] + bias[4*tx+0];
            r.y = acc[i*4+1] + bias[4*tx+1];
            r.z = acc[i*4+2] + bias[4*tx+2];
            r.w = acc[i*4+3] + bias[4*tx+3];
            if (res) { r.x += res[ob]; r.y += res[ob+1]; r.z += res[ob+2]; r.w += res[ob+3]; }
            *(float4*)&out[ob] = r;
        }
    }
}

// ---- 1x1 conv: out[b][o][n] = W[o][c] X[b][c][n] + b (+res); optional gelu on input ----
__global__ __launch_bounds__(256) void pw_kernel(
    const float* __restrict__ X1, const float* __restrict__ X2,
    const float* __restrict__ W, const float* __restrict__ bias,
    const float* __restrict__ res, float* __restrict__ out, int gelu_in)
{
    __shared__ float Xs[4096];
    __shared__ float Wt[64*68];
    int b = blockIdx.y, n0 = blockIdx.x << 6, tid = threadIdx.x;
    int ty = tid >> 4, tx = tid & 15;

    for (int idx = tid; idx < 4096; idx += 256) {
        int c = idx >> 6, nn = idx & 63;
        size_t g = ((size_t)(b*64 + c) << 12) + n0 + nn;
        float v = X1[g];
        if (X2) v += X2[g];
        if (gelu_in) v = gelu_f(v);
        Xs[idx] = v;
        Wt[nn*68 + c] = W[idx];
    }
    __syncthreads();

    u64 acc2[4][2];
    #pragma unroll
    for (int i = 0; i < 4; i++) { acc2[i][0] = 0ull; acc2[i][1] = 0ull; }
    #pragma unroll 8
    for (int c = 0; c < 64; c++) {
        float4 w = *(const float4*)&Wt[c*68 + 4*ty];
        ulonglong2 x2 = *(const ulonglong2*)&Xs[(c << 6) + 4*tx];
        float wf[4] = {w.x,w.y,w.z,w.w};
        #pragma unroll
        for (int i = 0; i < 4; i++) {
            u64 wd = pack2(wf[i], wf[i]);
            fma2(acc2[i][0], wd, x2.x);
            fma2(acc2[i][1], wd, x2.y);
        }
    }
    float acc[16];
    #pragma unroll
    for (int i = 0; i < 4; i++) {
        unpack2(acc2[i][0], acc[i*4+0], acc[i*4+1]);
        unpack2(acc2[i][1], acc[i*4+2], acc[i*4+3]);
    }

    #pragma unroll
    for (int i = 0; i < 4; i++) {
        int o = 4*ty + i;
        float bo_ = bias[o];
        size_t ob = ((size_t)(b*64 + o) << 12) + n0 + 4*tx;
        float4 r;
        r.x = acc[i*4+0] + bo_; r.y = acc[i*4+1] + bo_;
        r.z = acc[i*4+2] + bo_; r.w = acc[i*4+3] + bo_;
        if (res) { r.x += res[ob]; r.y += res[ob+1]; r.z += res[ob+2]; r.w += res[ob+3]; }
        *(float4*)&out[ob] = r;
    }
}

// ---- depthwise convs ----
__global__ __launch_bounds__(256) void dw5v_kernel(const float* __restrict__ X,
    const float* __restrict__ w, const float* __restrict__ bias, float* __restrict__ out)
{
    int idx = blockIdx.x*256 + threadIdx.x;
    int wc = idx & 63, h = (idx >> 6) & 63, c = (idx >> 12) & 63;
    const float* p = X + (idx & ~4095);
    float s = bias[c];
    #pragma unroll
    for (int t = 0; t < 5; t++) {
        int hh = h - 2 + t;
        if (hh >= 0 && hh < 64) s += w[c*5 + t] * p[(hh << 6) + wc];
    }
    out[idx] = s;
}

__global__ __launch_bounds__(256) void dw5h_kernel(const float* __restrict__ X,
    const float* __restrict__ w, const float* __restrict__ bias, float* __restrict__ out)
{
    int idx = blockIdx.x*256 + threadIdx.x;
    int wc = idx & 63, h = (idx >> 6) & 63, c = (idx >> 12) & 63;
    const float* p = X + (idx & ~4095);
    float s = bias[c];
    #pragma unroll
    for (int t = 0; t < 5; t++) {
        int ww = wc - 2 + t;
        if (ww >= 0 && ww < 64) s += w[c*5 + t] * p[(h << 6) + ww];
    }
    out[idx] = s;
}

__global__ __launch_bounds__(256) void dw33_kernel(const float* __restrict__ X,
    const float* __restrict__ w, const float* __restrict__ bias, float* __restrict__ out)
{
    int idx = blockIdx.x*256 + threadIdx.x;
    int wc = idx & 63, h = (idx >> 6) & 63, c = (idx >> 12) & 63;
    const float* p = X + (idx & ~4095);
    float s = bias[c];
    #pragma unroll
    for (int ky = 0; ky < 3; ky++) {
        int hh = h - 1 + ky;
        if (hh < 0 || hh >= 64) continue;
        #pragma unroll
        for (int kx = 0; kx < 3; kx++) {
            int ww = wc - 1 + kx;
            if (ww >= 0 && ww < 64) s += w[c*9 + ky*3 + kx] * p[(hh << 6) + ww];
        }
    }
    out[idx] = s;
}

// ---- LayerNorm over C; in [b][n][c], out [b][c][n] ----
__global__ __launch_bounds__(256) void ln_kernel(const float* __restrict__ X,
    const float* __restrict__ gam, const float* __restrict__ bet, float* __restrict__ out)
{
    __shared__ float Ts[64*66];
    int b = blockIdx.y, n0 = blockIdx.x << 6, tid = threadIdx.x;
    for (int idx = tid; idx < 4096; idx += 256) {
        int nn = idx >> 6, c = idx & 63;
        Ts[nn*66 + c] = X[((size_t)(b*4096 + n0 + nn)) * 64 + c];
    }
    __syncthreads();
    int row = tid >> 2, q = tid & 3;
    float s = 0.f, s2 = 0.f;
    #pragma unroll
    for (int k = 0; k < 16; k++) {
        float v = Ts[row*66 + q*16 + k];
        s += v; s2 += v*v;
    }
    s  += __shfl_xor_sync(0xffffffffu, s, 1);
    s  += __shfl_xor_sync(0xffffffffu, s, 2);
    s2 += __shfl_xor_sync(0xffffffffu, s2, 1);
    s2 += __shfl_xor_sync(0xffffffffu, s2, 2);
    float mu  = s * (1.0f/64.0f);
    float var = fmaxf(s2 * (1.0f/64.0f) - mu*mu, 0.f);
    float inv = rsqrtf(var + 1e-5f);
    #pragma unroll
    for (int k = 0; k < 16; k++) {
        int o = row*66 + q*16 + k;
        Ts[o] = (Ts[o] - mu) * inv;
    }
    __syncthreads();
    for (int idx = tid; idx < 4096; idx += 256) {
        int c = idx >> 6, nn = idx & 63;
        out[((size_t)(b*64 + c) << 12) + n0 + nn] = Ts[nn*66 + c] * gam[c] + bet[c];
    }
}

// ---- bilinear upsample x2, align_corners=True ----
__global__ __launch_bounds__(256) void up_kernel(const float* __restrict__ X,
                                                 float* __restrict__ out)
{
    int idx = blockIdx.x*256 + threadIdx.x;
    int wo = idx & 127, ho = (idx >> 7) & 127;
    int plane = idx >> 14;
    const float st = 63.0f / 127.0f;
    float fy = ho * st, fx = wo * st;
    int y0 = (int)fy, x0 = (int)fx;
    float wy = fy - y0, wx = fx - x0;
    int y1 = min(y0 + 1, 63), x1 = min(x0 + 1, 63);
    const float* p = X + (size_t)plane * 4096;
    float a = p[(y0 << 6) + x0], bv = p[(y1 << 6) + x0];
    float c = p[(y0 << 6) + x1], d = p[(y1 << 6) + x1];
    out[idx] = (a*(1.f - wy) + bv*wy)*(1.f - wx) + (c*(1.f - wy) + d*wy)*wx;
}

extern "C" void kernel_launch(void* const* d_in, const int* in_sizes, int n_in,
                              void* d_out, int out_size)
{
    const float* x       = (const float*)d_in[0];
    const float* Wq      = (const float*)d_in[1];
    const float* bq      = (const float*)d_in[2];
    const float* Wk      = (const float*)d_in[3];
    const float* bk      = (const float*)d_in[4];
    const float* Wv      = (const float*)d_in[5];
    const float* bv_     = (const float*)d_in[6];
    const float* Wl      = (const float*)d_in[7];
    const float* bl      = (const float*)d_in[8];
    const float* Wo      = (const float*)d_in[9];
    const float* bo      = (const float*)d_in[10];
    const float* Wp      = (const float*)d_in[11];
    const float* bp      = (const float*)d_in[12];
    const float* sch_dw  = (const float*)d_in[13];
    const float* sch_dwb = (const float*)d_in[14];
    const float* sch_pw  = (const float*)d_in[15];
    const float* sch_pwb = (const float*)d_in[16];
    const float* scv_dw  = (const float*)d_in[17];
    const float* scv_dwb = (const float*)d_in[18];
    const float* scv_pw  = (const float*)d_in[19];
    const float* scv_pwb = (const float*)d_in[20];
    const float* convh_w = (const float*)d_in[21];
    const float* convh_b = (const float*)d_in[22];
    const float* dsc_dw  = (const float*)d_in[23];
    const float* dsc_dwb = (const float*)d_in[24];
    const float* dsc_pw  = (const float*)d_in[25];
    const float* dsc_pwb = (const float*)d_in[26];
    const float* ln_g    = (const float*)d_in[27];
    const float* ln_b    = (const float*)d_in[28];
    float* out = (float*)d_out;

    float *xp, *gap, *qT, *kT, *v, *xV, *attn1, *plT, *t1, *t2, *xh, *xv2,
          *phT, *attn2, *prom, *pnorm, *dsc;
    cudaGetSymbolAddress((void**)&xp,    g_xp);
    cudaGetSymbolAddress((void**)&gap,   g_gap);
    cudaGetSymbolAddress((void**)&qT,    g_qT);
    cudaGetSymbolAddress((void**)&kT,    g_kT);
    cudaGetSymbolAddress((void**)&v,     g_v);
    cudaGetSymbolAddress((void**)&xV,    g_xV);
    cudaGetSymbolAddress((void**)&attn1, g_attn1);
    cudaGetSymbolAddress((void**)&plT,   g_plT);
    cudaGetSymbolAddress((void**)&t1,    g_t1);
    cudaGetSymbolAddress((void**)&t2,    g_t2);
    cudaGetSymbolAddress((void**)&xh,    g_xh);
    cudaGetSymbolAddress((void**)&xv2,   g_xv2);
    cudaGetSymbolAddress((void**)&phT,   g_phT);
    cudaGetSymbolAddress((void**)&attn2, g_attn2);
    cudaGetSymbolAddress((void**)&prom,  g_prom);
    cudaGetSymbolAddress((void**)&pnorm, g_pnorm);
    cudaGetSymbolAddress((void**)&dsc,   g_dsc);

    const int QKVV_SMEM = QKVV_SMEM_FLOATS * 4;
    static int attr_done = 0;
    if (!attr_done) {
        cudaFuncSetAttribute(qkvv_kernel, cudaFuncAttributeMaxDynamicSharedMemorySize, QKVV_SMEM);
        cudaFuncSetAttribute(attn_tc_kernel, cudaFuncAttributeMaxDynamicSharedMemorySize, ATTN_TC_SMEM);
        attr_done = 1;
    }

    pool_kernel<<<BB*CC, 256>>>(x, xp, gap);
    qkvv_kernel<<<dim3(64, BB), 256, QKVV_SMEM>>>(xp, gap, Wq, bq, Wk, bk, Wv, bv_, Wo, bo,
                                                  qT, kT, v, xV);
    attn_tc_kernel<<<dim3(32, BB), 256, ATTN_TC_SMEM>>>(qT, kT, v, attn1);
    lin_kernel<<<dim3(64, BB), 256>>>(attn1, Wl, bl, nullptr, plT, 1);
    dw5v_kernel<<<BB*CC*NN/256, 256>>>(xp, sch_dw, sch_dwb, t1);
    pw_kernel<<<dim3(64, BB), 256>>>(t1, nullptr, sch_pw, sch_pwb, nullptr, xh, 1);
    dw5h_kernel<<<BB*CC*NN/256, 256>>>(xp, scv_dw, scv_dwb, t2);
    pw_kernel<<<dim3(64, BB), 256>>>(t2, nullptr, scv_pw, scv_pwb, nullptr, xv2, 1);
    pw_kernel<<<dim3(64, BB), 256>>>(xh, xv2, convh_w, convh_b, nullptr, phT, 0);
    attn_tc_kernel<<<dim3(32, BB), 256, ATTN_TC_SMEM>>>(phT, plT, xV, attn2);
    lin_kernel<<<dim3(64, BB), 256>>>(attn2, Wp, bp, xV, prom, 0);
    ln_kernel<<<dim3(64, BB), 256>>>(prom, ln_g, ln_b, pnorm);
    dw33_kernel<<<BB*CC*NN/256, 256>>>(pnorm, dsc_dw, dsc_dwb, t1);
    pw_kernel<<<dim3(64, BB), 256>>>(t1, nullptr, dsc_pw, dsc_pwb, pnorm, dsc, 1);
    up_kernel<<<BB*CC*128*128/256, 256>>>(dsc, out);
}